// round 1
// baseline (speedup 1.0000x reference)
#include <cuda_runtime.h>
#include <cstdint>
#include <cfloat>

#define NHEAD 12
#define NB    4
#define SEQ   2048
#define HDIM  64
#define CDIM  768
#define CDIM3 2304
#define MROWS (NB*SEQ)   // 8192

// scratch (static device globals: no runtime allocation)
__device__ float g_q[NB*NHEAD*SEQ*HDIM];
__device__ float g_k[NB*NHEAD*SEQ*HDIM];
__device__ float g_v[NB*NHEAD*SEQ*HDIM];
__device__ float g_y[MROWS*CDIM];

__device__ __forceinline__ uint32_t f2tf(float f) {
    uint32_t u;
    asm("cvt.rna.tf32.f32 %0, %1;" : "=r"(u) : "f"(f));
    return u;
}

__device__ __forceinline__ void mma8(float* d,
    uint32_t a0, uint32_t a1, uint32_t a2, uint32_t a3,
    uint32_t b0, uint32_t b1) {
    asm volatile(
      "mma.sync.aligned.m16n8k8.row.col.f32.tf32.tf32.f32 "
      "{%0,%1,%2,%3}, {%4,%5,%6,%7}, {%8,%9}, {%0,%1,%2,%3};\n"
      : "+f"(d[0]), "+f"(d[1]), "+f"(d[2]), "+f"(d[3])
      : "r"(a0), "r"(a1), "r"(a2), "r"(a3), "r"(b0), "r"(b1));
}

// ---------------------------------------------------------------------------
// Kernel 1: qkv = x @ W_attn + b_attn, scattered to head-major q/k/v.
// q is pre-scaled by 0.125 (exact).
// Block tile 128(M) x 64(N) x 32(K), 256 threads (warps 4x2, warp tile 32x32).
// ---------------------------------------------------------------------------
__global__ __launch_bounds__(256) void qkv_gemm(
    const float* __restrict__ x, const float* __restrict__ W,
    const float* __restrict__ bias) {
    __shared__ uint32_t As[128*36];   // [m][k], stride 36 -> conflict-free A frags
    __shared__ uint32_t Bs[32*72];    // [k][n], stride 72 -> conflict-free B frags

    const int tid = threadIdx.x;
    const int wid = tid >> 5, lane = tid & 31;
    const int g = lane >> 2, tg = lane & 3;
    const int wM = wid & 3, wN = wid >> 2;
    const int rowBase = blockIdx.y * 128;
    const int colBase = blockIdx.x * 64;

    float acc[2][4][4];
    #pragma unroll
    for (int i = 0; i < 2; i++)
        #pragma unroll
        for (int j = 0; j < 4; j++)
            #pragma unroll
            for (int e = 0; e < 4; e++) acc[i][j][e] = 0.f;

    for (int kb = 0; kb < CDIM/32; kb++) {
        #pragma unroll
        for (int r = 0; r < 4; r++) {
            int m  = (tid >> 3) + r*32;
            int k4 = (tid & 7) * 4;
            float4 v = *(const float4*)(x + (size_t)(rowBase+m)*CDIM + kb*32 + k4);
            uint32_t* p = &As[m*36 + k4];
            p[0]=f2tf(v.x); p[1]=f2tf(v.y); p[2]=f2tf(v.z); p[3]=f2tf(v.w);
        }
        #pragma unroll
        for (int r = 0; r < 2; r++) {
            int k  = (tid >> 4) + r*16;
            int n4 = (tid & 15) * 4;
            float4 v = *(const float4*)(W + (size_t)(kb*32+k)*CDIM3 + colBase + n4);
            uint32_t* p = &Bs[k*72 + n4];
            p[0]=f2tf(v.x); p[1]=f2tf(v.y); p[2]=f2tf(v.z); p[3]=f2tf(v.w);
        }
        __syncthreads();
        #pragma unroll
        for (int kk = 0; kk < 4; kk++) {
            uint32_t a[2][4], bf[4][2];
            #pragma unroll
            for (int mt = 0; mt < 2; mt++) {
                int r0 = wM*32 + mt*16 + g;
                a[mt][0] = As[ r0     *36 + kk*8 + tg];
                a[mt][1] = As[(r0+8)  *36 + kk*8 + tg];
                a[mt][2] = As[ r0     *36 + kk*8 + tg + 4];
                a[mt][3] = As[(r0+8)  *36 + kk*8 + tg + 4];
            }
            #pragma unroll
            for (int nt = 0; nt < 4; nt++) {
                int c0 = wN*32 + nt*8 + g;
                bf[nt][0] = Bs[(kk*8+tg  )*72 + c0];
                bf[nt][1] = Bs[(kk*8+tg+4)*72 + c0];
            }
            #pragma unroll
            for (int mt = 0; mt < 2; mt++)
                #pragma unroll
                for (int nt = 0; nt < 4; nt++)
                    mma8(acc[mt][nt], a[mt][0],a[mt][1],a[mt][2],a[mt][3],
                         bf[nt][0], bf[nt][1]);
        }
        __syncthreads();
    }

    // epilogue: this 64-col block maps to exactly one of {q,k,v} and one head
    const int which = colBase / CDIM;
    const int cj = colBase % CDIM;
    const int h = cj >> 6;
    float* dst = (which == 0) ? g_q : (which == 1 ? g_k : g_v);
    const float qs = (which == 0) ? 0.125f : 1.0f;

    #pragma unroll
    for (int mt = 0; mt < 2; mt++) {
        int r0g = rowBase + wM*32 + mt*16 + g;
        int r1g = r0g + 8;
        int b0i = r0g >> 11, t0 = r0g & 2047;
        int b1i = r1g >> 11, t1 = r1g & 2047;
        size_t o0 = ((size_t)(b0i*NHEAD + h)*SEQ + t0)*HDIM;
        size_t o1 = ((size_t)(b1i*NHEAD + h)*SEQ + t1)*HDIM;
        #pragma unroll
        for (int nt = 0; nt < 4; nt++) {
            int d0 = wN*32 + nt*8 + tg*2;
            float bb0 = bias[colBase + d0];
            float bb1 = bias[colBase + d0 + 1];
            dst[o0 + d0    ] = (acc[mt][nt][0] + bb0) * qs;
            dst[o0 + d0 + 1] = (acc[mt][nt][1] + bb1) * qs;
            dst[o1 + d0    ] = (acc[mt][nt][2] + bb0) * qs;
            dst[o1 + d0 + 1] = (acc[mt][nt][3] + bb1) * qs;
        }
    }
}

// ---------------------------------------------------------------------------
// Kernel 2: flash attention with additive FIRE causal mask (mask carries -1e9
// above the diagonal, so only k-tiles with ks <= q_max are visited; skipped
// tiles contribute exactly 0). Br=128, Bc=64, 8 warps x 16 rows each.
// ---------------------------------------------------------------------------
#define FLASH_SMEM ((64*68 + 64*72 + 128*68) * 4)

__global__ __launch_bounds__(256, 2) void flash_attn(const float* __restrict__ mask) {
    extern __shared__ uint32_t sm[];
    uint32_t* Ks = sm;               // [64][68]
    uint32_t* Vs = Ks + 64*68;       // [64][72]
    uint32_t* Pb = Vs + 64*72;       // [128][68]

    const int tid = threadIdx.x;
    const int wid = tid >> 5, lane = tid & 31;
    const int g = lane >> 2, tg = lane & 3;
    const int qt = (int)(gridDim.x - 1 - blockIdx.x);   // heavy tiles first
    const int h = blockIdx.y >> 2, b = blockIdx.y & 3;
    const int rw = wid * 16;

    const float* Qg = g_q + ((size_t)((b*NHEAD + h)*SEQ) + qt*128)*HDIM;
    const float* Kg0 = g_k + (size_t)((b*NHEAD + h)*SEQ)*HDIM;
    const float* Vg0 = g_v + (size_t)((b*NHEAD + h)*SEQ)*HDIM;
    const float* Mb  = mask + ((size_t)h*SEQ + qt*128)*SEQ;

    // Q fragments held in registers for the whole block
    uint32_t qa[8][4];
    #pragma unroll
    for (int kk = 0; kk < 8; kk++) {
        qa[kk][0] = f2tf(Qg[(rw+g  )*HDIM + kk*8 + tg]);
        qa[kk][1] = f2tf(Qg[(rw+8+g)*HDIM + kk*8 + tg]);
        qa[kk][2] = f2tf(Qg[(rw+g  )*HDIM + kk*8 + tg + 4]);
        qa[kk][3] = f2tf(Qg[(rw+8+g)*HDIM + kk*8 + tg + 4]);
    }

    float o[8][4];
    #pragma unroll
    for (int nt = 0; nt < 8; nt++)
        #pragma unroll
        for (int e = 0; e < 4; e++) o[nt][e] = 0.f;
    float m0 = -FLT_MAX, m1 = -FLT_MAX, l0 = 0.f, l1 = 0.f;

    const int ktEnd = 2*qt + 1;
    for (int kt = 0; kt <= ktEnd; kt++) {
        __syncthreads();
        const float* Kg = Kg0 + (size_t)kt*64*HDIM;
        const float* Vg = Vg0 + (size_t)kt*64*HDIM;
        #pragma unroll
        for (int r = 0; r < 4; r++) {
            int row = (tid >> 4) + r*16;
            int c4  = (tid & 15) * 4;
            float4 kv = *(const float4*)(Kg + row*HDIM + c4);
            uint32_t* pk = &Ks[row*68 + c4];
            pk[0]=f2tf(kv.x); pk[1]=f2tf(kv.y); pk[2]=f2tf(kv.z); pk[3]=f2tf(kv.w);
            float4 vv = *(const float4*)(Vg + row*HDIM + c4);
            uint32_t* pv = &Vs[row*72 + c4];
            pv[0]=f2tf(vv.x); pv[1]=f2tf(vv.y); pv[2]=f2tf(vv.z); pv[3]=f2tf(vv.w);
        }
        __syncthreads();

        // S = Q K^T  (q pre-scaled by 1/sqrt(hd))
        float s[8][4];
        #pragma unroll
        for (int nt = 0; nt < 8; nt++)
            #pragma unroll
            for (int e = 0; e < 4; e++) s[nt][e] = 0.f;
        #pragma unroll
        for (int kk = 0; kk < 8; kk++) {
            #pragma unroll
            for (int nt = 0; nt < 8; nt++) {
                uint32_t b0 = Ks[(nt*8+g)*68 + kk*8 + tg];
                uint32_t b1 = Ks[(nt*8+g)*68 + kk*8 + tg + 4];
                mma8(s[nt], qa[kk][0], qa[kk][1], qa[kk][2], qa[kk][3], b0, b1);
            }
        }

        // + mask (direct from global; 32B-sector aligned per row)
        const float* M0 = Mb + (size_t)(rw+g)*SEQ + kt*64;
        const float* M1 = M0 + (size_t)8*SEQ;
        #pragma unroll
        for (int nt = 0; nt < 8; nt++) {
            int c = nt*8 + tg*2;
            s[nt][0] += M0[c];  s[nt][1] += M0[c+1];
            s[nt][2] += M1[c];  s[nt][3] += M1[c+1];
        }

        // online softmax (warp-local rows)
        float rm0 = -FLT_MAX, rm1 = -FLT_MAX;
        #pragma unroll
        for (int nt = 0; nt < 8; nt++) {
            rm0 = fmaxf(rm0, fmaxf(s[nt][0], s[nt][1]));
            rm1 = fmaxf(rm1, fmaxf(s[nt][2], s[nt][3]));
        }
        rm0 = fmaxf(rm0, __shfl_xor_sync(0xffffffffu, rm0, 1));
        rm0 = fmaxf(rm0, __shfl_xor_sync(0xffffffffu, rm0, 2));
        rm1 = fmaxf(rm1, __shfl_xor_sync(0xffffffffu, rm1, 1));
        rm1 = fmaxf(rm1, __shfl_xor_sync(0xffffffffu, rm1, 2));

        float mn0 = fmaxf(m0, rm0), mn1 = fmaxf(m1, rm1);
        float f0 = __expf(m0 - mn0), f1 = __expf(m1 - mn1);
        m0 = mn0; m1 = mn1;

        float rs0 = 0.f, rs1 = 0.f;
        #pragma unroll
        for (int nt = 0; nt < 8; nt++) {
            s[nt][0] = __expf(s[nt][0] - mn0);
            s[nt][1] = __expf(s[nt][1] - mn0);
            s[nt][2] = __expf(s[nt][2] - mn1);
            s[nt][3] = __expf(s[nt][3] - mn1);
            rs0 += s[nt][0] + s[nt][1];
            rs1 += s[nt][2] + s[nt][3];
        }
        l0 = l0*f0 + rs0;
        l1 = l1*f1 + rs1;
        #pragma unroll
        for (int nt = 0; nt < 8; nt++) {
            o[nt][0] *= f0; o[nt][1] *= f0;
            o[nt][2] *= f1; o[nt][3] *= f1;
        }

        // P -> warp-local smem (C-frag layout -> A-frag layout change)
        #pragma unroll
        for (int nt = 0; nt < 8; nt++) {
            int c = nt*8 + tg*2;
            Pb[(rw+g  )*68 + c    ] = f2tf(s[nt][0]);
            Pb[(rw+g  )*68 + c + 1] = f2tf(s[nt][1]);
            Pb[(rw+8+g)*68 + c    ] = f2tf(s[nt][2]);
            Pb[(rw+8+g)*68 + c + 1] = f2tf(s[nt][3]);
        }
        __syncwarp();

        // O += P V
        #pragma unroll
        for (int kk = 0; kk < 8; kk++) {
            uint32_t a0 = Pb[(rw+g  )*68 + kk*8 + tg];
            uint32_t a1 = Pb[(rw+8+g)*68 + kk*8 + tg];
            uint32_t a2 = Pb[(rw+g  )*68 + kk*8 + tg + 4];
            uint32_t a3 = Pb[(rw+8+g)*68 + kk*8 + tg + 4];
            #pragma unroll
            for (int nt = 0; nt < 8; nt++) {
                uint32_t b0 = Vs[(kk*8+tg  )*72 + nt*8 + g];
                uint32_t b1 = Vs[(kk*8+tg+4)*72 + nt*8 + g];
                mma8(o[nt], a0, a1, a2, a3, b0, b1);
            }
        }
    }

    // finalize: full row sums, divide, write to [B,T,C] scratch for proj GEMM
    l0 += __shfl_xor_sync(0xffffffffu, l0, 1);
    l0 += __shfl_xor_sync(0xffffffffu, l0, 2);
    l1 += __shfl_xor_sync(0xffffffffu, l1, 1);
    l1 += __shfl_xor_sync(0xffffffffu, l1, 2);
    float inv0 = 1.f / l0, inv1 = 1.f / l1;

    int r0 = qt*128 + rw + g, r1 = r0 + 8;
    float* y0 = g_y + (size_t)(b*SEQ + r0)*CDIM + h*HDIM;
    float* y1 = g_y + (size_t)(b*SEQ + r1)*CDIM + h*HDIM;
    #pragma unroll
    for (int nt = 0; nt < 8; nt++) {
        int c = nt*8 + tg*2;
        y0[c]   = o[nt][0]*inv0;  y0[c+1] = o[nt][1]*inv0;
        y1[c]   = o[nt][2]*inv1;  y1[c+1] = o[nt][3]*inv1;
    }
}

// ---------------------------------------------------------------------------
// Kernel 3: out = y @ W_proj + b_proj     (same tiling as kernel 1)
// ---------------------------------------------------------------------------
__global__ __launch_bounds__(256) void proj_gemm(
    const float* __restrict__ W, const float* __restrict__ bias,
    float* __restrict__ out) {
    __shared__ uint32_t As[128*36];
    __shared__ uint32_t Bs[32*72];

    const int tid = threadIdx.x;
    const int wid = tid >> 5, lane = tid & 31;
    const int g = lane >> 2, tg = lane & 3;
    const int wM = wid & 3, wN = wid >> 2;
    const int rowBase = blockIdx.y * 128;
    const int colBase = blockIdx.x * 64;
    const float* A = g_y;

    float acc[2][4][4];
    #pragma unroll
    for (int i = 0; i < 2; i++)
        #pragma unroll
        for (int j = 0; j < 4; j++)
            #pragma unroll
            for (int e = 0; e < 4; e++) acc[i][j][e] = 0.f;

    for (int kb = 0; kb < CDIM/32; kb++) {
        #pragma unroll
        for (int r = 0; r < 4; r++) {
            int m  = (tid >> 3) + r*32;
            int k4 = (tid & 7) * 4;
            float4 v = *(const float4*)(A + (size_t)(rowBase+m)*CDIM + kb*32 + k4);
            uint32_t* p = &As[m*36 + k4];
            p[0]=f2tf(v.x); p[1]=f2tf(v.y); p[2]=f2tf(v.z); p[3]=f2tf(v.w);
        }
        #pragma unroll
        for (int r = 0; r < 2; r++) {
            int k  = (tid >> 4) + r*16;
            int n4 = (tid & 15) * 4;
            float4 v = *(const float4*)(W + (size_t)(kb*32+k)*CDIM + colBase + n4);
            uint32_t* p = &Bs[k*72 + n4];
            p[0]=f2tf(v.x); p[1]=f2tf(v.y); p[2]=f2tf(v.z); p[3]=f2tf(v.w);
        }
        __syncthreads();
        #pragma unroll
        for (int kk = 0; kk < 4; kk++) {
            uint32_t a[2][4], bf[4][2];
            #pragma unroll
            for (int mt = 0; mt < 2; mt++) {
                int r0 = wM*32 + mt*16 + g;
                a[mt][0] = As[ r0    *36 + kk*8 + tg];
                a[mt][1] = As[(r0+8) *36 + kk*8 + tg];
                a[mt][2] = As[ r0    *36 + kk*8 + tg + 4];
                a[mt][3] = As[(r0+8) *36 + kk*8 + tg + 4];
            }
            #pragma unroll
            for (int nt = 0; nt < 4; nt++) {
                int c0 = wN*32 + nt*8 + g;
                bf[nt][0] = Bs[(kk*8+tg  )*72 + c0];
                bf[nt][1] = Bs[(kk*8+tg+4)*72 + c0];
            }
            #pragma unroll
            for (int mt = 0; mt < 2; mt++)
                #pragma unroll
                for (int nt = 0; nt < 4; nt++)
                    mma8(acc[mt][nt], a[mt][0],a[mt][1],a[mt][2],a[mt][3],
                         bf[nt][0], bf[nt][1]);
        }
        __syncthreads();
    }

    #pragma unroll
    for (int mt = 0; mt < 2; mt++) {
        int r0g = rowBase + wM*32 + mt*16 + g;
        int r1g = r0g + 8;
        #pragma unroll
        for (int nt = 0; nt < 4; nt++) {
            int j = colBase + wN*32 + nt*8 + tg*2;
            float bb0 = bias[j], bb1 = bias[j+1];
            out[(size_t)r0g*CDIM + j    ] = acc[mt][nt][0] + bb0;
            out[(size_t)r0g*CDIM + j + 1] = acc[mt][nt][1] + bb1;
            out[(size_t)r1g*CDIM + j    ] = acc[mt][nt][2] + bb0;
            out[(size_t)r1g*CDIM + j + 1] = acc[mt][nt][3] + bb1;
        }
    }
}

extern "C" void kernel_launch(void* const* d_in, const int* in_sizes, int n_in,
                              void* d_out, int out_size) {
    const float* x      = (const float*)d_in[0];
    const float* mask   = (const float*)d_in[1];
    const float* W_attn = (const float*)d_in[2];
    const float* b_attn = (const float*)d_in[3];
    const float* W_proj = (const float*)d_in[4];
    const float* b_proj = (const float*)d_in[5];
    float* out = (float*)d_out;

    cudaFuncSetAttribute((const void*)flash_attn,
                         cudaFuncAttributeMaxDynamicSharedMemorySize, FLASH_SMEM);

    dim3 g1(CDIM3/64, MROWS/128);      // 36 x 64
    qkv_gemm<<<g1, 256>>>(x, W_attn, b_attn);

    dim3 g2(SEQ/128, NHEAD*NB);        // 16 x 48  (y = h*4 + b for mask L2 reuse)
    flash_attn<<<g2, 256, FLASH_SMEM>>>(mask);

    dim3 g3(CDIM/64, MROWS/128);       // 12 x 64
    proj_gemm<<<g3, 256>>>(W_proj, b_proj, out);
}

// round 2
// speedup vs baseline: 1.0084x; 1.0084x over previous
#include <cuda_runtime.h>
#include <cstdint>
#include <cfloat>

#define NHEAD 12
#define NB    4
#define SEQ   2048
#define HDIM  64
#define CDIM  768
#define CDIM3 2304
#define MROWS (NB*SEQ)   // 8192

// scratch (static device globals: no runtime allocation)
__device__ float g_q[NB*NHEAD*SEQ*HDIM];
__device__ float g_k[NB*NHEAD*SEQ*HDIM];
__device__ float g_v[NB*NHEAD*SEQ*HDIM];
__device__ float g_y[MROWS*CDIM];

__device__ __forceinline__ uint32_t f2tf(float f) {
    uint32_t u;
    asm("cvt.rna.tf32.f32 %0, %1;" : "=r"(u) : "f"(f));
    return u;
}

__device__ __forceinline__ void mma8(float* d,
    uint32_t a0, uint32_t a1, uint32_t a2, uint32_t a3,
    uint32_t b0, uint32_t b1) {
    asm volatile(
      "mma.sync.aligned.m16n8k8.row.col.f32.tf32.tf32.f32 "
      "{%0,%1,%2,%3}, {%4,%5,%6,%7}, {%8,%9}, {%0,%1,%2,%3};\n"
      : "+f"(d[0]), "+f"(d[1]), "+f"(d[2]), "+f"(d[3])
      : "r"(a0), "r"(a1), "r"(a2), "r"(a3), "r"(b0), "r"(b1));
}

// ---------------------------------------------------------------------------
// Kernel 1: qkv = x @ W_attn + b_attn, scattered to head-major q/k/v.
// q is pre-scaled by 0.125 (exact).
// Block tile 128(M) x 64(N) x 32(K), 256 threads (warps 4x2, warp tile 32x32).
// ---------------------------------------------------------------------------
__global__ __launch_bounds__(256) void qkv_gemm(
    const float* __restrict__ x, const float* __restrict__ W,
    const float* __restrict__ bias) {
    __shared__ uint32_t As[128*36];   // [m][k], stride 36 -> conflict-free A frags
    __shared__ uint32_t Bs[32*72];    // [k][n], stride 72 -> conflict-free B frags

    const int tid = threadIdx.x;
    const int wid = tid >> 5, lane = tid & 31;
    const int g = lane >> 2, tg = lane & 3;
    const int wM = wid & 3, wN = wid >> 2;
    const int rowBase = blockIdx.y * 128;
    const int colBase = blockIdx.x * 64;

    float acc[2][4][4];
    #pragma unroll
    for (int i = 0; i < 2; i++)
        #pragma unroll
        for (int j = 0; j < 4; j++)
            #pragma unroll
            for (int e = 0; e < 4; e++) acc[i][j][e] = 0.f;

    for (int kb = 0; kb < CDIM/32; kb++) {
        #pragma unroll
        for (int r = 0; r < 4; r++) {
            int m  = (tid >> 3) + r*32;
            int k4 = (tid & 7) * 4;
            float4 v = *(const float4*)(x + (size_t)(rowBase+m)*CDIM + kb*32 + k4);
            uint32_t* p = &As[m*36 + k4];
            p[0]=f2tf(v.x); p[1]=f2tf(v.y); p[2]=f2tf(v.z); p[3]=f2tf(v.w);
        }
        #pragma unroll
        for (int r = 0; r < 2; r++) {
            int k  = (tid >> 4) + r*16;
            int n4 = (tid & 15) * 4;
            float4 v = *(const float4*)(W + (size_t)(kb*32+k)*CDIM3 + colBase + n4);
            uint32_t* p = &Bs[k*72 + n4];
            p[0]=f2tf(v.x); p[1]=f2tf(v.y); p[2]=f2tf(v.z); p[3]=f2tf(v.w);
        }
        __syncthreads();
        #pragma unroll
        for (int kk = 0; kk < 4; kk++) {
            uint32_t a[2][4], bf[4][2];
            #pragma unroll
            for (int mt = 0; mt < 2; mt++) {
                int r0 = wM*32 + mt*16 + g;
                a[mt][0] = As[ r0     *36 + kk*8 + tg];
                a[mt][1] = As[(r0+8)  *36 + kk*8 + tg];
                a[mt][2] = As[ r0     *36 + kk*8 + tg + 4];
                a[mt][3] = As[(r0+8)  *36 + kk*8 + tg + 4];
            }
            #pragma unroll
            for (int nt = 0; nt < 4; nt++) {
                int c0 = wN*32 + nt*8 + g;
                bf[nt][0] = Bs[(kk*8+tg  )*72 + c0];
                bf[nt][1] = Bs[(kk*8+tg+4)*72 + c0];
            }
            #pragma unroll
            for (int mt = 0; mt < 2; mt++)
                #pragma unroll
                for (int nt = 0; nt < 4; nt++)
                    mma8(acc[mt][nt], a[mt][0],a[mt][1],a[mt][2],a[mt][3],
                         bf[nt][0], bf[nt][1]);
        }
        __syncthreads();
    }

    // epilogue: this 64-col block maps to exactly one of {q,k,v} and one head
    const int which = colBase / CDIM;
    const int cj = colBase % CDIM;
    const int h = cj >> 6;
    float* dst = (which == 0) ? g_q : (which == 1 ? g_k : g_v);
    const float qs = (which == 0) ? 0.125f : 1.0f;

    #pragma unroll
    for (int mt = 0; mt < 2; mt++) {
        int r0g = rowBase + wM*32 + mt*16 + g;
        int r1g = r0g + 8;
        int b0i = r0g >> 11, t0 = r0g & 2047;
        int b1i = r1g >> 11, t1 = r1g & 2047;
        size_t o0 = ((size_t)(b0i*NHEAD + h)*SEQ + t0)*HDIM;
        size_t o1 = ((size_t)(b1i*NHEAD + h)*SEQ + t1)*HDIM;
        #pragma unroll
        for (int nt = 0; nt < 4; nt++) {
            int d0 = wN*32 + nt*8 + tg*2;
            float bb0 = bias[colBase + d0];
            float bb1 = bias[colBase + d0 + 1];
            dst[o0 + d0    ] = (acc[mt][nt][0] + bb0) * qs;
            dst[o0 + d0 + 1] = (acc[mt][nt][1] + bb1) * qs;
            dst[o1 + d0    ] = (acc[mt][nt][2] + bb0) * qs;
            dst[o1 + d0 + 1] = (acc[mt][nt][3] + bb1) * qs;
        }
    }
}

// ---------------------------------------------------------------------------
// Kernel 2: flash attention with additive FIRE causal mask (mask carries -1e9
// above the diagonal, so only k-tiles with ks <= q_max are visited; skipped
// tiles contribute exactly 0). Br=128, Bc=64, 8 warps x 16 rows each.
// ---------------------------------------------------------------------------
#define FLASH_SMEM ((64*68 + 64*72 + 128*68) * 4)

__global__ __launch_bounds__(256, 2) void flash_attn(const float* __restrict__ mask) {
    extern __shared__ uint32_t sm[];
    uint32_t* Ks = sm;               // [64][68]
    uint32_t* Vs = Ks + 64*68;       // [64][72]
    uint32_t* Pb = Vs + 64*72;       // [128][68]

    const int tid = threadIdx.x;
    const int wid = tid >> 5, lane = tid & 31;
    const int g = lane >> 2, tg = lane & 3;
    const int qt = (int)(gridDim.x - 1 - blockIdx.x);   // heavy tiles first
    const int h = blockIdx.y >> 2, b = blockIdx.y & 3;
    const int rw = wid * 16;

    const float* Qg = g_q + ((size_t)((b*NHEAD + h)*SEQ) + qt*128)*HDIM;
    const float* Kg0 = g_k + (size_t)((b*NHEAD + h)*SEQ)*HDIM;
    const float* Vg0 = g_v + (size_t)((b*NHEAD + h)*SEQ)*HDIM;
    const float* Mb  = mask + ((size_t)h*SEQ + qt*128)*SEQ;

    // Q fragments held in registers for the whole block
    uint32_t qa[8][4];
    #pragma unroll
    for (int kk = 0; kk < 8; kk++) {
        qa[kk][0] = f2tf(Qg[(rw+g  )*HDIM + kk*8 + tg]);
        qa[kk][1] = f2tf(Qg[(rw+8+g)*HDIM + kk*8 + tg]);
        qa[kk][2] = f2tf(Qg[(rw+g  )*HDIM + kk*8 + tg + 4]);
        qa[kk][3] = f2tf(Qg[(rw+8+g)*HDIM + kk*8 + tg + 4]);
    }

    float o[8][4];
    #pragma unroll
    for (int nt = 0; nt < 8; nt++)
        #pragma unroll
        for (int e = 0; e < 4; e++) o[nt][e] = 0.f;
    float m0 = -FLT_MAX, m1 = -FLT_MAX, l0 = 0.f, l1 = 0.f;

    const int ktEnd = 2*qt + 1;
    for (int kt = 0; kt <= ktEnd; kt++) {
        __syncthreads();
        const float* Kg = Kg0 + (size_t)kt*64*HDIM;
        const float* Vg = Vg0 + (size_t)kt*64*HDIM;
        #pragma unroll
        for (int r = 0; r < 4; r++) {
            int row = (tid >> 4) + r*16;
            int c4  = (tid & 15) * 4;
            float4 kv = *(const float4*)(Kg + row*HDIM + c4);
            uint32_t* pk = &Ks[row*68 + c4];
            pk[0]=f2tf(kv.x); pk[1]=f2tf(kv.y); pk[2]=f2tf(kv.z); pk[3]=f2tf(kv.w);
            float4 vv = *(const float4*)(Vg + row*HDIM + c4);
            uint32_t* pv = &Vs[row*72 + c4];
            pv[0]=f2tf(vv.x); pv[1]=f2tf(vv.y); pv[2]=f2tf(vv.z); pv[3]=f2tf(vv.w);
        }
        __syncthreads();

        // S = Q K^T  (q pre-scaled by 1/sqrt(hd))
        float s[8][4];
        #pragma unroll
        for (int nt = 0; nt < 8; nt++)
            #pragma unroll
            for (int e = 0; e < 4; e++) s[nt][e] = 0.f;
        #pragma unroll
        for (int kk = 0; kk < 8; kk++) {
            #pragma unroll
            for (int nt = 0; nt < 8; nt++) {
                uint32_t b0 = Ks[(nt*8+g)*68 + kk*8 + tg];
                uint32_t b1 = Ks[(nt*8+g)*68 + kk*8 + tg + 4];
                mma8(s[nt], qa[kk][0], qa[kk][1], qa[kk][2], qa[kk][3], b0, b1);
            }
        }

        // + mask (direct from global; 32B-sector aligned per row)
        const float* M0 = Mb + (size_t)(rw+g)*SEQ + kt*64;
        const float* M1 = M0 + (size_t)8*SEQ;
        #pragma unroll
        for (int nt = 0; nt < 8; nt++) {
            int c = nt*8 + tg*2;
            s[nt][0] += M0[c];  s[nt][1] += M0[c+1];
            s[nt][2] += M1[c];  s[nt][3] += M1[c+1];
        }

        // online softmax (warp-local rows)
        float rm0 = -FLT_MAX, rm1 = -FLT_MAX;
        #pragma unroll
        for (int nt = 0; nt < 8; nt++) {
            rm0 = fmaxf(rm0, fmaxf(s[nt][0], s[nt][1]));
            rm1 = fmaxf(rm1, fmaxf(s[nt][2], s[nt][3]));
        }
        rm0 = fmaxf(rm0, __shfl_xor_sync(0xffffffffu, rm0, 1));
        rm0 = fmaxf(rm0, __shfl_xor_sync(0xffffffffu, rm0, 2));
        rm1 = fmaxf(rm1, __shfl_xor_sync(0xffffffffu, rm1, 1));
        rm1 = fmaxf(rm1, __shfl_xor_sync(0xffffffffu, rm1, 2));

        float mn0 = fmaxf(m0, rm0), mn1 = fmaxf(m1, rm1);
        float f0 = __expf(m0 - mn0), f1 = __expf(m1 - mn1);
        m0 = mn0; m1 = mn1;

        float rs0 = 0.f, rs1 = 0.f;
        #pragma unroll
        for (int nt = 0; nt < 8; nt++) {
            s[nt][0] = __expf(s[nt][0] - mn0);
            s[nt][1] = __expf(s[nt][1] - mn0);
            s[nt][2] = __expf(s[nt][2] - mn1);
            s[nt][3] = __expf(s[nt][3] - mn1);
            rs0 += s[nt][0] + s[nt][1];
            rs1 += s[nt][2] + s[nt][3];
        }
        l0 = l0*f0 + rs0;
        l1 = l1*f1 + rs1;
        #pragma unroll
        for (int nt = 0; nt < 8; nt++) {
            o[nt][0] *= f0; o[nt][1] *= f0;
            o[nt][2] *= f1; o[nt][3] *= f1;
        }

        // P -> warp-local smem (C-frag layout -> A-frag layout change)
        #pragma unroll
        for (int nt = 0; nt < 8; nt++) {
            int c = nt*8 + tg*2;
            Pb[(rw+g  )*68 + c    ] = f2tf(s[nt][0]);
            Pb[(rw+g  )*68 + c + 1] = f2tf(s[nt][1]);
            Pb[(rw+8+g)*68 + c    ] = f2tf(s[nt][2]);
            Pb[(rw+8+g)*68 + c + 1] = f2tf(s[nt][3]);
        }
        __syncwarp();

        // O += P V
        #pragma unroll
        for (int kk = 0; kk < 8; kk++) {
            uint32_t a0 = Pb[(rw+g  )*68 + kk*8 + tg];
            uint32_t a1 = Pb[(rw+8+g)*68 + kk*8 + tg];
            uint32_t a2 = Pb[(rw+g  )*68 + kk*8 + tg + 4];
            uint32_t a3 = Pb[(rw+8+g)*68 + kk*8 + tg + 4];
            #pragma unroll
            for (int nt = 0; nt < 8; nt++) {
                uint32_t b0 = Vs[(kk*8+tg  )*72 + nt*8 + g];
                uint32_t b1 = Vs[(kk*8+tg+4)*72 + nt*8 + g];
                mma8(o[nt], a0, a1, a2, a3, b0, b1);
            }
        }
    }

    // finalize: full row sums, divide, write to [B,T,C] scratch for proj GEMM
    l0 += __shfl_xor_sync(0xffffffffu, l0, 1);
    l0 += __shfl_xor_sync(0xffffffffu, l0, 2);
    l1 += __shfl_xor_sync(0xffffffffu, l1, 1);
    l1 += __shfl_xor_sync(0xffffffffu, l1, 2);
    float inv0 = 1.f / l0, inv1 = 1.f / l1;

    int r0 = qt*128 + rw + g, r1 = r0 + 8;
    float* y0 = g_y + (size_t)(b*SEQ + r0)*CDIM + h*HDIM;
    float* y1 = g_y + (size_t)(b*SEQ + r1)*CDIM + h*HDIM;
    #pragma unroll
    for (int nt = 0; nt < 8; nt++) {
        int c = nt*8 + tg*2;
        y0[c]   = o[nt][0]*inv0;  y0[c+1] = o[nt][1]*inv0;
        y1[c]   = o[nt][2]*inv1;  y1[c+1] = o[nt][3]*inv1;
    }
}

// ---------------------------------------------------------------------------
// Kernel 3: out = y @ W_proj + b_proj     (same tiling as kernel 1)
// ---------------------------------------------------------------------------
__global__ __launch_bounds__(256) void proj_gemm(
    const float* __restrict__ W, const float* __restrict__ bias,
    float* __restrict__ out) {
    __shared__ uint32_t As[128*36];
    __shared__ uint32_t Bs[32*72];

    const int tid = threadIdx.x;
    const int wid = tid >> 5, lane = tid & 31;
    const int g = lane >> 2, tg = lane & 3;
    const int wM = wid & 3, wN = wid >> 2;
    const int rowBase = blockIdx.y * 128;
    const int colBase = blockIdx.x * 64;
    const float* A = g_y;

    float acc[2][4][4];
    #pragma unroll
    for (int i = 0; i < 2; i++)
        #pragma unroll
        for (int j = 0; j < 4; j++)
            #pragma unroll
            for (int e = 0; e < 4; e++) acc[i][j][e] = 0.f;

    for (int kb = 0; kb < CDIM/32; kb++) {
        #pragma unroll
        for (int r = 0; r < 4; r++) {
            int m  = (tid >> 3) + r*32;
            int k4 = (tid & 7) * 4;
            float4 v = *(const float4*)(A + (size_t)(rowBase+m)*CDIM + kb*32 + k4);
            uint32_t* p = &As[m*36 + k4];
            p[0]=f2tf(v.x); p[1]=f2tf(v.y); p[2]=f2tf(v.z); p[3]=f2tf(v.w);
        }
        #pragma unroll
        for (int r = 0; r < 2; r++) {
            int k  = (tid >> 4) + r*16;
            int n4 = (tid & 15) * 4;
            float4 v = *(const float4*)(W + (size_t)(kb*32+k)*CDIM + colBase + n4);
            uint32_t* p = &Bs[k*72 + n4];
            p[0]=f2tf(v.x); p[1]=f2tf(v.y); p[2]=f2tf(v.z); p[3]=f2tf(v.w);
        }
        __syncthreads();
        #pragma unroll
        for (int kk = 0; kk < 4; kk++) {
            uint32_t a[2][4], bf[4][2];
            #pragma unroll
            for (int mt = 0; mt < 2; mt++) {
                int r0 = wM*32 + mt*16 + g;
                a[mt][0] = As[ r0    *36 + kk*8 + tg];
                a[mt][1] = As[(r0+8) *36 + kk*8 + tg];
                a[mt][2] = As[ r0    *36 + kk*8 + tg + 4];
                a[mt][3] = As[(r0+8) *36 + kk*8 + tg + 4];
            }
            #pragma unroll
            for (int nt = 0; nt < 4; nt++) {
                int c0 = wN*32 + nt*8 + g;
                bf[nt][0] = Bs[(kk*8+tg  )*72 + c0];
                bf[nt][1] = Bs[(kk*8+tg+4)*72 + c0];
            }
            #pragma unroll
            for (int mt = 0; mt < 2; mt++)
                #pragma unroll
                for (int nt = 0; nt < 4; nt++)
                    mma8(acc[mt][nt], a[mt][0],a[mt][1],a[mt][2],a[mt][3],
                         bf[nt][0], bf[nt][1]);
        }
        __syncthreads();
    }

    #pragma unroll
    for (int mt = 0; mt < 2; mt++) {
        int r0g = rowBase + wM*32 + mt*16 + g;
        int r1g = r0g + 8;
        #pragma unroll
        for (int nt = 0; nt < 4; nt++) {
            int j = colBase + wN*32 + nt*8 + tg*2;
            float bb0 = bias[j], bb1 = bias[j+1];
            out[(size_t)r0g*CDIM + j    ] = acc[mt][nt][0] + bb0;
            out[(size_t)r0g*CDIM + j + 1] = acc[mt][nt][1] + bb1;
            out[(size_t)r1g*CDIM + j    ] = acc[mt][nt][2] + bb0;
            out[(size_t)r1g*CDIM + j + 1] = acc[mt][nt][3] + bb1;
        }
    }
}

extern "C" void kernel_launch(void* const* d_in, const int* in_sizes, int n_in,
                              void* d_out, int out_size) {
    const float* x      = (const float*)d_in[0];
    const float* mask   = (const float*)d_in[1];
    const float* W_attn = (const float*)d_in[2];
    const float* b_attn = (const float*)d_in[3];
    const float* W_proj = (const float*)d_in[4];
    const float* b_proj = (const float*)d_in[5];
    float* out = (float*)d_out;

    cudaFuncSetAttribute((const void*)flash_attn,
                         cudaFuncAttributeMaxDynamicSharedMemorySize, FLASH_SMEM);

    dim3 g1(CDIM3/64, MROWS/128);      // 36 x 64
    qkv_gemm<<<g1, 256>>>(x, W_attn, b_attn);

    dim3 g2(SEQ/128, NHEAD*NB);        // 16 x 48  (y = h*4 + b for mask L2 reuse)
    flash_attn<<<g2, 256, FLASH_SMEM>>>(mask);

    dim3 g3(CDIM/64, MROWS/128);       // 12 x 64
    proj_gemm<<<g3, 256>>>(W_proj, b_proj, out);
}